// round 6
// baseline (speedup 1.0000x reference)
#include <cuda_runtime.h>

#define NT 256
typedef unsigned long long ull;

// Problem constants: B=256, T=16, O=32, E=32, I=32, H=HL=64, TE=512, EI=64, P=496

struct Params {
    const float* z;
    const float *ee1_w,*ee1_b,*ee2_w,*ee2_b,*ee3_w,*ee3_b;
    const float *ne1_w,*ne1_b,*ne2_w,*ne2_b,*ne3_w,*ne3_b,*ne4_w,*ne4_b;
    const float *le1_w,*le1_b,*le2_w,*le2_b,*le3_w,*le3_b;
    const float *lt1_w,*lt1_b,*lt2_w,*lt2_b,*lt3_w,*lt3_b,*lt4_w,*lt4_b,*lt5_w,*lt5_b;
    float* out;
    int t_future;
};

// ---- packed f32x2 primitives (SASS FFMA2 path, PTX-only) ----
__device__ __forceinline__ ull pack2(float lo, float hi) {
    ull r;
    asm("mov.b64 %0, {%1, %2};" : "=l"(r) : "f"(lo), "f"(hi));
    return r;
}
__device__ __forceinline__ ull dup2(float x) {
    ull r;
    asm("mov.b64 %0, {%1, %1};" : "=l"(r) : "f"(x));
    return r;
}
__device__ __forceinline__ ull fma2(ull a, ull b, ull c) {
    ull d;
    asm("fma.rn.f32x2 %0, %1, %2, %3;" : "=l"(d) : "l"(a), "l"(b), "l"(c));
    return d;
}
__device__ __forceinline__ void unpack2(ull p, float& lo, float& hi) {
    asm("mov.b64 {%0, %1}, %2;" : "=f"(lo), "=f"(hi) : "l"(p));
}

__device__ __forceinline__ void fma4(float acc[4], float a, const float4& w) {
    acc[0] = fmaf(a, w.x, acc[0]);
    acc[1] = fmaf(a, w.y, acc[1]);
    acc[2] = fmaf(a, w.z, acc[2]);
    acc[3] = fmaf(a, w.w, acc[3]);
}

// out[32][64] (optionally +=) = in[32][IN] @ W[IN][64] (+bias) (optional relu)
// 256 threads: 2 rows x 4 cols per thread, packed f32x2 accumulators.
template<int IN, bool ACC, bool RELU>
__device__ __forceinline__ void layer32x64(const float* __restrict__ in,
                                           const float* __restrict__ W,
                                           const float* __restrict__ bias,
                                           float* __restrict__ out, int tid)
{
    const int c0 = (tid & 15) * 4;
    const int r0 = (tid >> 4) * 2;
    ull a0p[2], a1p[2];
    if (ACC) {
        a0p[0] = pack2(out[r0*64+c0+0], out[r0*64+c0+1]);
        a0p[1] = pack2(out[r0*64+c0+2], out[r0*64+c0+3]);
        a1p[0] = pack2(out[(r0+1)*64+c0+0], out[(r0+1)*64+c0+1]);
        a1p[1] = pack2(out[(r0+1)*64+c0+2], out[(r0+1)*64+c0+3]);
    } else if (bias) {
        ull b0 = pack2(bias[c0+0], bias[c0+1]);
        ull b1 = pack2(bias[c0+2], bias[c0+3]);
        a0p[0] = b0; a0p[1] = b1; a1p[0] = b0; a1p[1] = b1;
    } else {
        a0p[0] = 0ull; a0p[1] = 0ull; a1p[0] = 0ull; a1p[1] = 0ull;
    }
    const float* in0 = in + r0 * IN;
    const float* in1 = in0 + IN;
#pragma unroll 4
    for (int k = 0; k < IN; k += 4) {
        float4 x0 = *(const float4*)(in0 + k);
        float4 x1 = *(const float4*)(in1 + k);
#define LKK(comp, kk) { \
        ulonglong2 w = *(const ulonglong2*)(W + (k + kk) * 64 + c0); \
        ull d0 = dup2(x0.comp), d1 = dup2(x1.comp); \
        a0p[0] = fma2(d0, w.x, a0p[0]); a0p[1] = fma2(d0, w.y, a0p[1]); \
        a1p[0] = fma2(d1, w.x, a1p[0]); a1p[1] = fma2(d1, w.y, a1p[1]); }
        LKK(x, 0) LKK(y, 1) LKK(z, 2) LKK(w, 3)
#undef LKK
    }
    float v00, v01, v02, v03, v10, v11, v12, v13;
    unpack2(a0p[0], v00, v01); unpack2(a0p[1], v02, v03);
    unpack2(a1p[0], v10, v11); unpack2(a1p[1], v12, v13);
    if (RELU) {
        v00 = fmaxf(v00, 0.f); v01 = fmaxf(v01, 0.f); v02 = fmaxf(v02, 0.f); v03 = fmaxf(v03, 0.f);
        v10 = fmaxf(v10, 0.f); v11 = fmaxf(v11, 0.f); v12 = fmaxf(v12, 0.f); v13 = fmaxf(v13, 0.f);
    }
    *(float4*)(out + r0 * 64 + c0) = make_float4(v00, v01, v02, v03);
    *(float4*)(out + (r0 + 1) * 64 + c0) = make_float4(v10, v11, v12, v13);
}

#define H2S 68   // padded stride for h2 (16B-aligned, bank-conflict-free scatter)

// h2[128][H2S] = relu(h1[128][64] @ W[64][64] + bias). h1 smem, W/bias global.
// 256 threads: 4 rows x 8 cols per thread, packed f32x2.
__device__ __forceinline__ void gemm128(const float* __restrict__ A,
                                        const float* __restrict__ Wg,
                                        const float* __restrict__ bias,
                                        float* __restrict__ Cout, int tid)
{
    const int c0 = (tid & 7) * 8;
    const int r0 = (tid >> 3) * 4;     // 0..124
    ull bp0 = pack2(bias[c0+0], bias[c0+1]);
    ull bp1 = pack2(bias[c0+2], bias[c0+3]);
    ull bp2 = pack2(bias[c0+4], bias[c0+5]);
    ull bp3 = pack2(bias[c0+6], bias[c0+7]);
    ull acc[4][4];
#pragma unroll
    for (int r = 0; r < 4; r++) {
        acc[r][0] = bp0; acc[r][1] = bp1; acc[r][2] = bp2; acc[r][3] = bp3;
    }
    const float* A0 = A + r0 * 64;
#pragma unroll 2
    for (int k = 0; k < 64; k += 4) {
        float4 a0 = *(const float4*)(A0 + k);
        float4 a1 = *(const float4*)(A0 + 64 + k);
        float4 a2 = *(const float4*)(A0 + 128 + k);
        float4 a3 = *(const float4*)(A0 + 192 + k);
#define GKK(comp, kk) { \
        const float* wr = Wg + (k + kk) * 64 + c0; \
        ulonglong2 wA = *(const ulonglong2*)(wr); \
        ulonglong2 wB = *(const ulonglong2*)(wr + 4); \
        ull d0 = dup2(a0.comp), d1 = dup2(a1.comp), d2 = dup2(a2.comp), d3 = dup2(a3.comp); \
        acc[0][0] = fma2(d0, wA.x, acc[0][0]); acc[0][1] = fma2(d0, wA.y, acc[0][1]); \
        acc[0][2] = fma2(d0, wB.x, acc[0][2]); acc[0][3] = fma2(d0, wB.y, acc[0][3]); \
        acc[1][0] = fma2(d1, wA.x, acc[1][0]); acc[1][1] = fma2(d1, wA.y, acc[1][1]); \
        acc[1][2] = fma2(d1, wB.x, acc[1][2]); acc[1][3] = fma2(d1, wB.y, acc[1][3]); \
        acc[2][0] = fma2(d2, wA.x, acc[2][0]); acc[2][1] = fma2(d2, wA.y, acc[2][1]); \
        acc[2][2] = fma2(d2, wB.x, acc[2][2]); acc[2][3] = fma2(d2, wB.y, acc[2][3]); \
        acc[3][0] = fma2(d3, wA.x, acc[3][0]); acc[3][1] = fma2(d3, wA.y, acc[3][1]); \
        acc[3][2] = fma2(d3, wB.x, acc[3][2]); acc[3][3] = fma2(d3, wB.y, acc[3][3]); }
        GKK(x, 0) GKK(y, 1) GKK(z, 2) GKK(w, 3)
#undef GKK
    }
#pragma unroll
    for (int r = 0; r < 4; r++) {
        float v0, v1, v2, v3, v4, v5, v6, v7;
        unpack2(acc[r][0], v0, v1); unpack2(acc[r][1], v2, v3);
        unpack2(acc[r][2], v4, v5); unpack2(acc[r][3], v6, v7);
        float* cr = Cout + (r0 + r) * H2S + c0;
        *(float4*)cr = make_float4(fmaxf(v0, 0.f), fmaxf(v1, 0.f), fmaxf(v2, 0.f), fmaxf(v3, 0.f));
        *(float4*)(cr + 4) = make_float4(fmaxf(v4, 0.f), fmaxf(v5, 0.f), fmaxf(v6, 0.f), fmaxf(v7, 0.f));
    }
}

// agg[32][64] = G[32][64] @ W3[64][64] + (31-2n)*b3   (scatter bias correction)
__device__ __forceinline__ void aggGemm(const float* __restrict__ G,
                                        const float* __restrict__ W3,
                                        const float* __restrict__ b3,
                                        float* __restrict__ agg, int tid)
{
    const int c0 = (tid & 15) * 4;
    const int r0 = (tid >> 4) * 2;
    const float sc0 = (float)(31 - 2 * r0);
    const float sc1 = (float)(31 - 2 * (r0 + 1));
    float acc0[4], acc1[4];
#pragma unroll
    for (int j = 0; j < 4; j++) {
        float bvv = b3[c0 + j];
        acc0[j] = sc0 * bvv; acc1[j] = sc1 * bvv;
    }
    const float* g0 = G + r0 * 64;
    const float* g1 = g0 + 64;
#pragma unroll 4
    for (int k = 0; k < 64; k += 4) {
        float4 a0 = *(const float4*)(g0 + k);
        float4 a1 = *(const float4*)(g1 + k);
        float4 w0 = *(const float4*)(W3 + (k + 0) * 64 + c0);
        float4 w1 = *(const float4*)(W3 + (k + 1) * 64 + c0);
        float4 w2 = *(const float4*)(W3 + (k + 2) * 64 + c0);
        float4 w3 = *(const float4*)(W3 + (k + 3) * 64 + c0);
        fma4(acc0, a0.x, w0); fma4(acc0, a0.y, w1); fma4(acc0, a0.z, w2); fma4(acc0, a0.w, w3);
        fma4(acc1, a1.x, w0); fma4(acc1, a1.y, w1); fma4(acc1, a1.z, w2); fma4(acc1, a1.w, w3);
    }
#pragma unroll
    for (int j = 0; j < 4; j++) {
        agg[r0 * 64 + c0 + j] = acc0[j];
        agg[(r0 + 1) * 64 + c0 + j] = acc1[j];
    }
}

// small generic layer: out[32][OUT] = relu?(in[32][IN] @ W + b)
__device__ __forceinline__ void layer_small(const float* __restrict__ in, int IN,
                                            const float* __restrict__ W,
                                            const float* __restrict__ bias,
                                            float* __restrict__ out, int OUT,
                                            bool relu, int tid)
{
    for (int idx = tid; idx < 32 * OUT; idx += NT) {
        int r = idx / OUT, c = idx % OUT;
        float acc = bias[c];
        const float* inr = in + r * IN;
#pragma unroll 4
        for (int k = 0; k < IN; k++) acc = fmaf(inr[k], W[k * OUT + c], acc);
        out[idx] = relu ? fmaxf(acc, 0.f) : acc;
    }
}

// accumulate one 64-k chunk into packed accumulators:
// accp[2 rows][2 col-pairs] += src[32][64] @ Wg[64][64] (Wg global)
__device__ __forceinline__ void acc_chunk_p(const float* __restrict__ src,
                                            const float* __restrict__ Wg,
                                            ull a0p[2], ull a1p[2],
                                            int r0, int c0)
{
    const float* in0 = src + r0 * 64;
    const float* in1 = in0 + 64;
#pragma unroll 4
    for (int k = 0; k < 64; k += 4) {
        float4 x0 = *(const float4*)(in0 + k);
        float4 x1 = *(const float4*)(in1 + k);
#define AKK(comp, kk) { \
        ulonglong2 w = *(const ulonglong2*)(Wg + (k + kk) * 64 + c0); \
        ull d0 = dup2(x0.comp), d1 = dup2(x1.comp); \
        a0p[0] = fma2(d0, w.x, a0p[0]); a0p[1] = fma2(d0, w.y, a0p[1]); \
        a1p[0] = fma2(d1, w.x, a1p[0]); a1p[1] = fma2(d1, w.y, a1p[1]); }
        AKK(x, 0) AKK(y, 1) AKK(z, 2) AKK(w, 3)
#undef AKK
    }
}

// edge block: ya/yb[32][64] smem -> agg[32][64]. W2/W3 from global (L1-resident).
// 4 windows of 128 pairs; sparse signed scatter in registers (8 cols/thread).
__device__ __forceinline__ void edge_block(const float* ya, const float* yb,
                                           const float* __restrict__ b1,
                                           const float* __restrict__ W2g, const float* __restrict__ b2,
                                           const float* __restrict__ W3g, const float* __restrict__ b3,
                                           float* h1, float* h2, float* Gs, float* agg,
                                           const unsigned char* ii, const unsigned char* jj,
                                           const unsigned short* jl,
                                           int tid)
{
    const int n   = tid >> 3;          // 0..31
    const int c0s = (tid & 7) * 8;
    const int rs    = n * 31 - ((n * (n - 1)) >> 1);  // first pair with ii==n
    const int iiend = rs + 31 - n;
    float g[8];
#pragma unroll
    for (int j = 0; j < 8; j++) g[j] = 0.f;
    int kcur = 0;

#pragma unroll 1
    for (int ch = 0; ch < 4; ch++) {
        const int p0 = ch * 128;
        // h1 = relu(ya[ii] + yb[jj] + b1) for this 128-pair window
        for (int idx = tid; idx < 128 * 64; idx += NT) {
            int pl = idx >> 6, c = idx & 63;
            int p = p0 + pl;
            float v = ya[ii[p] * 64 + c] + yb[jj[p] * 64 + c] + b1[c];
            h1[idx] = fmaxf(v, 0.f);
        }
        __syncthreads();
        gemm128(h1, W2g, b2, h2, tid);
        __syncthreads();
        // signed sparse scatter into register G
        int lo = max(rs, p0), hi = min(iiend, p0 + 128);
        for (int p = lo; p < hi; p++) {
            const float* r = h2 + (p - p0) * H2S + c0s;
            float4 v0 = *(const float4*)(r);
            float4 v1 = *(const float4*)(r + 4);
            g[0] += v0.x; g[1] += v0.y; g[2] += v0.z; g[3] += v0.w;
            g[4] += v1.x; g[5] += v1.y; g[6] += v1.z; g[7] += v1.w;
        }
        while (kcur < n) {
            int p = jl[(n << 5) + kcur];
            if (p >= p0 + 128) break;
            const float* r = h2 + (p - p0) * H2S + c0s;
            float4 v0 = *(const float4*)(r);
            float4 v1 = *(const float4*)(r + 4);
            g[0] -= v0.x; g[1] -= v0.y; g[2] -= v0.z; g[3] -= v0.w;
            g[4] -= v1.x; g[5] -= v1.y; g[6] -= v1.z; g[7] -= v1.w;
            kcur++;
        }
    }
#pragma unroll
    for (int j = 0; j < 8; j++) Gs[n * 64 + c0s + j] = g[j];
    __syncthreads();
    aggGemm(Gs, W3g, b3, agg, tid);
    __syncthreads();
}

// smem layout (float offsets)
#define OFF_H1   0       // 128*64
#define OFF_H2   8192    // 128*68
#define OFF_YA   16896   // 32*64
#define OFF_YB   18944
#define OFF_AGG  20992
#define OFF_ZC   23040
#define SMEM_FLOATS 25088
#define SMEM_BYTES  (SMEM_FLOATS * 4 + 2048 + 1024)  // + jl(u16 x1024) + ii/jj

__global__ void __launch_bounds__(NT, 2)
RelationalLatentDynamics_82849919140105_kernel(Params P)
{
    extern __shared__ float sm[];
    float* s_h1  = sm + OFF_H1;
    float* s_h2  = sm + OFF_H2;
    float* s_ya  = sm + OFF_YA;
    float* s_yb  = sm + OFF_YB;
    float* s_agg = sm + OFF_AGG;
    float* s_zc  = sm + OFF_ZC;
    unsigned short* s_jl = (unsigned short*)(sm + SMEM_FLOATS);
    unsigned char*  s_ii = (unsigned char*)(s_jl + 1024);
    unsigned char*  s_jj = s_ii + 512;

    const int tid = threadIdx.x;
    const int b = blockIdx.x;
    const int c0 = (tid & 15) * 4;
    const int r0 = (tid >> 4) * 2;

    // pair index tables (padded to 512)
    for (int p = tid; p < 512; p += NT) {
        if (p < 496) {
            int pp = p, i = 0;
            while (pp >= 31 - i) { pp -= 31 - i; i++; }
            s_ii[p] = (unsigned char)i;
            s_jj[p] = (unsigned char)(i + 1 + pp);
        } else {
            s_ii[p] = 0; s_jj[p] = 1;
        }
    }
    // jl[n][k] = index of pair (k, n) for k < n (ascending in k)
    for (int idx = tid; idx < 1024; idx += NT) {
        int n = idx >> 5, k = idx & 31;
        s_jl[idx] = (k < n)
            ? (unsigned short)(k * 31 - ((k * (k - 1)) >> 1) + (n - k - 1))
            : (unsigned short)0xFFFF;
    }

    const float* zb = P.z + (size_t)b * (16 * 32 * 32);

    // ---- Phase A: ya/yb = src @ ee1_w (streamed src chunks, packed reg acc) ----
    {
        ull A0p[2] = {0ull, 0ull}, A1p[2] = {0ull, 0ull};
        ull B0p[2] = {0ull, 0ull}, B1p[2] = {0ull, 0ull};
#pragma unroll 1
        for (int ch = 0; ch < 8; ch++) {
            for (int idx = tid; idx < 2048; idx += NT) {
                int o = idx >> 6, fl = idx & 63;
                int t = 2 * ch + (fl >> 5), e = fl & 31;
                float v = zb[(t * 32 + o) * 32 + e];
                if (t > 0) v -= zb[((t - 1) * 32 + o) * 32 + e];
                s_h1[o * 64 + fl] = v;
            }
            __syncthreads();
            acc_chunk_p(s_h1, P.ee1_w + ch * 4096, A0p, A1p, r0, c0);
            acc_chunk_p(s_h1, P.ee1_w + 512 * 64 + ch * 4096, B0p, B1p, r0, c0);
            __syncthreads();
        }
        float v0, v1, v2, v3;
        unpack2(A0p[0], v0, v1); unpack2(A0p[1], v2, v3);
        *(float4*)(s_ya + r0 * 64 + c0) = make_float4(v0, v1, v2, v3);
        unpack2(A1p[0], v0, v1); unpack2(A1p[1], v2, v3);
        *(float4*)(s_ya + (r0 + 1) * 64 + c0) = make_float4(v0, v1, v2, v3);
        unpack2(B0p[0], v0, v1); unpack2(B0p[1], v2, v3);
        *(float4*)(s_yb + r0 * 64 + c0) = make_float4(v0, v1, v2, v3);
        unpack2(B1p[0], v0, v1); unpack2(B1p[1], v2, v3);
        *(float4*)(s_yb + (r0 + 1) * 64 + c0) = make_float4(v0, v1, v2, v3);
    }
    __syncthreads();

    // ---- ee edge block ----
    edge_block(s_ya, s_yb, P.ee1_b, P.ee2_w, P.ee2_b, P.ee3_w, P.ee3_b,
               s_h1, s_h2, s_yb, s_agg, s_ii, s_jj, s_jl, tid);

    // ---- ne MLP ----
    layer32x64<64, false, false>(s_agg, P.ne1_w + 512 * 64, P.ne1_b, s_ya, tid);
    {
        ull c0p[2], c1p[2];
        c0p[0] = pack2(s_ya[r0*64+c0+0], s_ya[r0*64+c0+1]);          // own cells
        c0p[1] = pack2(s_ya[r0*64+c0+2], s_ya[r0*64+c0+3]);
        c1p[0] = pack2(s_ya[(r0+1)*64+c0+0], s_ya[(r0+1)*64+c0+1]);
        c1p[1] = pack2(s_ya[(r0+1)*64+c0+2], s_ya[(r0+1)*64+c0+3]);
#pragma unroll 1
        for (int ch = 0; ch < 8; ch++) {
            for (int idx = tid; idx < 2048; idx += NT) {
                int o = idx >> 6, fl = idx & 63;
                int t = 2 * ch + (fl >> 5), e = fl & 31;
                float v = zb[(t * 32 + o) * 32 + e];
                if (t > 0) v -= zb[((t - 1) * 32 + o) * 32 + e];
                s_h1[o * 64 + fl] = v;
            }
            __syncthreads();
            acc_chunk_p(s_h1, P.ne1_w + ch * 4096, c0p, c1p, r0, c0);
            __syncthreads();
        }
        float v0, v1, v2, v3;
        unpack2(c0p[0], v0, v1); unpack2(c0p[1], v2, v3);
        *(float4*)(s_ya + r0 * 64 + c0) =
            make_float4(fmaxf(v0, 0.f), fmaxf(v1, 0.f), fmaxf(v2, 0.f), fmaxf(v3, 0.f));
        unpack2(c1p[0], v0, v1); unpack2(c1p[1], v2, v3);
        *(float4*)(s_ya + (r0 + 1) * 64 + c0) =
            make_float4(fmaxf(v0, 0.f), fmaxf(v1, 0.f), fmaxf(v2, 0.f), fmaxf(v3, 0.f));
    }
    __syncthreads();
    layer32x64<64, false, true>(s_ya, P.ne2_w, P.ne2_b, s_h1, tid);
    __syncthreads();
    layer_small(s_h1, 64, P.ne3_w, P.ne3_b, s_h2, 32, true, tid);
    __syncthreads();
    layer_small(s_h2, 32, P.ne4_w, P.ne4_b, s_h1, 32, false, tid);  // z_impl
    __syncthreads();

    // zc = concat(z[b,-1], z_impl)
    const float* zlast = zb + 15 * 32 * 32;
    for (int idx = tid; idx < 2048; idx += NT) {
        int o = idx >> 6, c = idx & 63;
        s_zc[idx] = (c < 32) ? zlast[o * 32 + c] : s_h1[o * 32 + (c - 32)];
    }
    __syncthreads();

    // ---- rollout ----
    float* outb = P.out + (size_t)b * (P.t_future * 32 * 32);
#pragma unroll 1
    for (int t = 0; t < P.t_future; t++) {
        layer32x64<64, false, false>(s_zc, P.le1_w,           nullptr, s_ya, tid);
        layer32x64<64, false, false>(s_zc, P.le1_w + 64 * 64, nullptr, s_yb, tid);
        __syncthreads();
        edge_block(s_ya, s_yb, P.le1_b, P.le2_w, P.le2_b, P.le3_w, P.le3_b,
                   s_h1, s_h2, s_yb, s_agg, s_ii, s_jj, s_jl, tid);

        layer32x64<64, false, false>(s_zc,  P.lt1_w,           P.lt1_b, s_h1, tid);
        layer32x64<64, true,  true >(s_agg, P.lt1_w + 64 * 64, nullptr, s_h1, tid);
        __syncthreads();
        layer32x64<64, false, true>(s_h1, P.lt2_w, P.lt2_b, s_h2, tid);
        __syncthreads();
        layer_small(s_h2, 64, P.lt3_w, P.lt3_b, s_h1, 32, true, tid);
        __syncthreads();
        layer_small(s_h1, 32, P.lt4_w, P.lt4_b, s_h2, 16, true, tid);
        __syncthreads();
        layer32x64<16, false, false>(s_h2, P.lt5_w, P.lt5_b, s_h1, tid);  // delta
        __syncthreads();

        for (int idx = tid; idx < 2048; idx += NT) {
            float zn = s_zc[idx] + s_h1[idx];
            s_zc[idx] = zn;
            int o = idx >> 6, c = idx & 63;
            if (c < 32) outb[t * 1024 + o * 32 + c] = zn;
        }
        __syncthreads();
    }
}

extern "C" void kernel_launch(void* const* d_in, const int* in_sizes, int n_in,
                              void* d_out, int out_size)
{
    Params P;
    int i = 0;
    P.z     = (const float*)d_in[i++];
    P.ee1_w = (const float*)d_in[i++]; P.ee1_b = (const float*)d_in[i++];
    P.ee2_w = (const float*)d_in[i++]; P.ee2_b = (const float*)d_in[i++];
    P.ee3_w = (const float*)d_in[i++]; P.ee3_b = (const float*)d_in[i++];
    P.ne1_w = (const float*)d_in[i++]; P.ne1_b = (const float*)d_in[i++];
    P.ne2_w = (const float*)d_in[i++]; P.ne2_b = (const float*)d_in[i++];
    P.ne3_w = (const float*)d_in[i++]; P.ne3_b = (const float*)d_in[i++];
    P.ne4_w = (const float*)d_in[i++]; P.ne4_b = (const float*)d_in[i++];
    P.le1_w = (const float*)d_in[i++]; P.le1_b = (const float*)d_in[i++];
    P.le2_w = (const float*)d_in[i++]; P.le2_b = (const float*)d_in[i++];
    P.le3_w = (const float*)d_in[i++]; P.le3_b = (const float*)d_in[i++];
    P.lt1_w = (const float*)d_in[i++]; P.lt1_b = (const float*)d_in[i++];
    P.lt2_w = (const float*)d_in[i++]; P.lt2_b = (const float*)d_in[i++];
    P.lt3_w = (const float*)d_in[i++]; P.lt3_b = (const float*)d_in[i++];
    P.lt4_w = (const float*)d_in[i++]; P.lt4_b = (const float*)d_in[i++];
    P.lt5_w = (const float*)d_in[i++]; P.lt5_b = (const float*)d_in[i++];
    P.out = (float*)d_out;
    P.t_future = out_size / (256 * 32 * 32);

    cudaFuncSetAttribute(RelationalLatentDynamics_82849919140105_kernel,
                         cudaFuncAttributeMaxDynamicSharedMemorySize, SMEM_BYTES);
    RelationalLatentDynamics_82849919140105_kernel<<<256, NT, SMEM_BYTES>>>(P);
}

// round 7
// speedup vs baseline: 1.2393x; 1.2393x over previous
#include <cuda_runtime.h>

#define NT 256

// B=256, T=16, O=32, E=32, I=32, H=HL=64, TE=512, EI=64, P=496
// One CTA processes TWO batches (grid=128), interleaved for ILP.

struct Params {
    const float* z;
    const float *ee1_w,*ee1_b,*ee2_w,*ee2_b,*ee3_w,*ee3_b;
    const float *ne1_w,*ne1_b,*ne2_w,*ne2_b,*ne3_w,*ne3_b,*ne4_w,*ne4_b;
    const float *le1_w,*le1_b,*le2_w,*le2_b,*le3_w,*le3_b;
    const float *lt1_w,*lt1_b,*lt2_w,*lt2_b,*lt3_w,*lt3_b,*lt4_w,*lt4_b,*lt5_w,*lt5_b;
    float* out;
    int t_future;
};

__device__ __forceinline__ void fma4(float acc[4], float a, const float4& w) {
    acc[0] = fmaf(a, w.x, acc[0]);
    acc[1] = fmaf(a, w.y, acc[1]);
    acc[2] = fmaf(a, w.z, acc[2]);
    acc[3] = fmaf(a, w.w, acc[3]);
}

// two-batch 32x64 layer: outX (opt +=) = inX[32][IN] @ W[IN][64] (+bias) (opt relu)
// 256 threads: 2 rows x 4 cols per thread per batch; W loads shared.
template<int IN, bool ACC, bool RELU>
__device__ __forceinline__ void layer2(const float* __restrict__ in0,
                                       const float* __restrict__ in1,
                                       const float* __restrict__ W,
                                       const float* __restrict__ bias,
                                       float* __restrict__ out0,
                                       float* __restrict__ out1, int tid)
{
    const int c0 = (tid & 15) * 4;
    const int r0 = (tid >> 4) * 2;
    float acc[2][2][4];
    if (ACC) {
#pragma unroll
        for (int i = 0; i < 2; i++)
#pragma unroll
            for (int j = 0; j < 4; j++) {
                acc[0][i][j] = out0[(r0 + i) * 64 + c0 + j];
                acc[1][i][j] = out1[(r0 + i) * 64 + c0 + j];
            }
    } else {
#pragma unroll
        for (int j = 0; j < 4; j++) {
            float bv = bias ? bias[c0 + j] : 0.f;
            acc[0][0][j] = bv; acc[0][1][j] = bv;
            acc[1][0][j] = bv; acc[1][1][j] = bv;
        }
    }
    const float* i00 = in0 + r0 * IN;
    const float* i01 = i00 + IN;
    const float* i10 = in1 + r0 * IN;
    const float* i11 = i10 + IN;
#pragma unroll 4
    for (int k = 0; k < IN; k += 4) {
        float4 w0 = *(const float4*)(W + (k + 0) * 64 + c0);
        float4 w1 = *(const float4*)(W + (k + 1) * 64 + c0);
        float4 w2 = *(const float4*)(W + (k + 2) * 64 + c0);
        float4 w3 = *(const float4*)(W + (k + 3) * 64 + c0);
        float4 a;
        a = *(const float4*)(i00 + k);
        fma4(acc[0][0], a.x, w0); fma4(acc[0][0], a.y, w1); fma4(acc[0][0], a.z, w2); fma4(acc[0][0], a.w, w3);
        a = *(const float4*)(i01 + k);
        fma4(acc[0][1], a.x, w0); fma4(acc[0][1], a.y, w1); fma4(acc[0][1], a.z, w2); fma4(acc[0][1], a.w, w3);
        a = *(const float4*)(i10 + k);
        fma4(acc[1][0], a.x, w0); fma4(acc[1][0], a.y, w1); fma4(acc[1][0], a.z, w2); fma4(acc[1][0], a.w, w3);
        a = *(const float4*)(i11 + k);
        fma4(acc[1][1], a.x, w0); fma4(acc[1][1], a.y, w1); fma4(acc[1][1], a.z, w2); fma4(acc[1][1], a.w, w3);
    }
#pragma unroll
    for (int i = 0; i < 2; i++)
#pragma unroll
        for (int j = 0; j < 4; j++) {
            float v0 = acc[0][i][j], v1 = acc[1][i][j];
            if (RELU) { v0 = fmaxf(v0, 0.f); v1 = fmaxf(v1, 0.f); }
            out0[(r0 + i) * 64 + c0 + j] = v0;
            out1[(r0 + i) * 64 + c0 + j] = v1;
        }
}

#define H2S 68   // padded h2 stride

// two-batch 64x64x64 gemm: h2X[64][H2S] = relu(h1X[64][64] @ Ws[64][64] + b2)
// 4 rows x 4 cols per thread per batch; Ws in smem, loads shared across batches.
__device__ __forceinline__ void gemm64_2(const float* __restrict__ A0,
                                         const float* __restrict__ A1,
                                         const float* __restrict__ Ws,
                                         const float* __restrict__ b2,
                                         float* __restrict__ C0,
                                         float* __restrict__ C1, int tid)
{
    const int c0 = (tid & 15) * 4;
    const int r0 = (tid >> 4) * 4;
    float acc[2][4][4];
#pragma unroll
    for (int j = 0; j < 4; j++) {
        float bv = b2[c0 + j];
#pragma unroll
        for (int i = 0; i < 4; i++) { acc[0][i][j] = bv; acc[1][i][j] = bv; }
    }
#pragma unroll 2
    for (int k = 0; k < 64; k += 4) {
        float4 w0 = *(const float4*)(Ws + (k + 0) * 64 + c0);
        float4 w1 = *(const float4*)(Ws + (k + 1) * 64 + c0);
        float4 w2 = *(const float4*)(Ws + (k + 2) * 64 + c0);
        float4 w3 = *(const float4*)(Ws + (k + 3) * 64 + c0);
#pragma unroll
        for (int i = 0; i < 4; i++) {
            float4 a = *(const float4*)(A0 + (r0 + i) * 64 + k);
            fma4(acc[0][i], a.x, w0); fma4(acc[0][i], a.y, w1);
            fma4(acc[0][i], a.z, w2); fma4(acc[0][i], a.w, w3);
            float4 b = *(const float4*)(A1 + (r0 + i) * 64 + k);
            fma4(acc[1][i], b.x, w0); fma4(acc[1][i], b.y, w1);
            fma4(acc[1][i], b.z, w2); fma4(acc[1][i], b.w, w3);
        }
    }
#pragma unroll
    for (int i = 0; i < 4; i++)
#pragma unroll
        for (int j = 0; j < 4; j++) {
            C0[(r0 + i) * H2S + c0 + j] = fmaxf(acc[0][i][j], 0.f);
            C1[(r0 + i) * H2S + c0 + j] = fmaxf(acc[1][i][j], 0.f);
        }
}

// two-batch agg: aggX[32][64] = GX[32][64] @ Ws3[64][64] + (31-2n)*b3
__device__ __forceinline__ void aggGemm_2(const float* __restrict__ G0,
                                          const float* __restrict__ G1,
                                          const float* __restrict__ Ws3,
                                          const float* __restrict__ b3,
                                          float* __restrict__ agg0,
                                          float* __restrict__ agg1, int tid)
{
    const int c0 = (tid & 15) * 4;
    const int r0 = (tid >> 4) * 2;
    const float sc0 = (float)(31 - 2 * r0);
    const float sc1 = (float)(31 - 2 * (r0 + 1));
    float acc[2][2][4];
#pragma unroll
    for (int j = 0; j < 4; j++) {
        float bv = b3[c0 + j];
        acc[0][0][j] = sc0 * bv; acc[0][1][j] = sc1 * bv;
        acc[1][0][j] = sc0 * bv; acc[1][1][j] = sc1 * bv;
    }
#pragma unroll 4
    for (int k = 0; k < 64; k += 4) {
        float4 w0 = *(const float4*)(Ws3 + (k + 0) * 64 + c0);
        float4 w1 = *(const float4*)(Ws3 + (k + 1) * 64 + c0);
        float4 w2 = *(const float4*)(Ws3 + (k + 2) * 64 + c0);
        float4 w3 = *(const float4*)(Ws3 + (k + 3) * 64 + c0);
        float4 a;
        a = *(const float4*)(G0 + r0 * 64 + k);
        fma4(acc[0][0], a.x, w0); fma4(acc[0][0], a.y, w1); fma4(acc[0][0], a.z, w2); fma4(acc[0][0], a.w, w3);
        a = *(const float4*)(G0 + (r0 + 1) * 64 + k);
        fma4(acc[0][1], a.x, w0); fma4(acc[0][1], a.y, w1); fma4(acc[0][1], a.z, w2); fma4(acc[0][1], a.w, w3);
        a = *(const float4*)(G1 + r0 * 64 + k);
        fma4(acc[1][0], a.x, w0); fma4(acc[1][0], a.y, w1); fma4(acc[1][0], a.z, w2); fma4(acc[1][0], a.w, w3);
        a = *(const float4*)(G1 + (r0 + 1) * 64 + k);
        fma4(acc[1][1], a.x, w0); fma4(acc[1][1], a.y, w1); fma4(acc[1][1], a.z, w2); fma4(acc[1][1], a.w, w3);
    }
#pragma unroll
    for (int i = 0; i < 2; i++)
#pragma unroll
        for (int j = 0; j < 4; j++) {
            agg0[(r0 + i) * 64 + c0 + j] = acc[0][i][j];
            agg1[(r0 + i) * 64 + c0 + j] = acc[1][i][j];
        }
}

// two-batch small layer: outX[32][OUT] = relu?(inX[32][IN] @ W + b); W loads shared
__device__ __forceinline__ void layer_small_2(const float* __restrict__ in0,
                                              const float* __restrict__ in1, int IN,
                                              const float* __restrict__ W,
                                              const float* __restrict__ bias,
                                              float* __restrict__ out0,
                                              float* __restrict__ out1, int OUT,
                                              bool relu, int tid)
{
    for (int idx = tid; idx < 32 * OUT; idx += NT) {
        int r = idx / OUT, c = idx % OUT;
        float a0 = bias[c], a1 = a0;
        const float* i0 = in0 + r * IN;
        const float* i1 = in1 + r * IN;
#pragma unroll 4
        for (int k = 0; k < IN; k++) {
            float w = W[k * OUT + c];
            a0 = fmaf(i0[k], w, a0);
            a1 = fmaf(i1[k], w, a1);
        }
        out0[idx] = relu ? fmaxf(a0, 0.f) : a0;
        out1[idx] = relu ? fmaxf(a1, 0.f) : a1;
    }
}

// two-batch streamed k-chunk accumulate: acc[bb][row][col] += sX[32][64] @ Wg[64][64]
__device__ __forceinline__ void acc_chunk2(const float* __restrict__ s0,
                                           const float* __restrict__ s1,
                                           const float* __restrict__ Wg,
                                           float acc[2][2][4], int r0, int c0)
{
    const float* a00 = s0 + r0 * 64;
    const float* a01 = a00 + 64;
    const float* a10 = s1 + r0 * 64;
    const float* a11 = a10 + 64;
#pragma unroll 4
    for (int k = 0; k < 64; k += 4) {
        float4 w0 = *(const float4*)(Wg + (k + 0) * 64 + c0);
        float4 w1 = *(const float4*)(Wg + (k + 1) * 64 + c0);
        float4 w2 = *(const float4*)(Wg + (k + 2) * 64 + c0);
        float4 w3 = *(const float4*)(Wg + (k + 3) * 64 + c0);
        float4 a;
        a = *(const float4*)(a00 + k);
        fma4(acc[0][0], a.x, w0); fma4(acc[0][0], a.y, w1); fma4(acc[0][0], a.z, w2); fma4(acc[0][0], a.w, w3);
        a = *(const float4*)(a01 + k);
        fma4(acc[0][1], a.x, w0); fma4(acc[0][1], a.y, w1); fma4(acc[0][1], a.z, w2); fma4(acc[0][1], a.w, w3);
        a = *(const float4*)(a10 + k);
        fma4(acc[1][0], a.x, w0); fma4(acc[1][0], a.y, w1); fma4(acc[1][0], a.z, w2); fma4(acc[1][0], a.w, w3);
        a = *(const float4*)(a11 + k);
        fma4(acc[1][1], a.x, w0); fma4(acc[1][1], a.y, w1); fma4(acc[1][1], a.z, w2); fma4(acc[1][1], a.w, w3);
    }
}

// two-batch edge block. b1 pre-folded into ya. W2/W3 in smem.
__device__ __forceinline__ void edge_block_2(const float* ya0, const float* ya1,
                                             const float* yb0, const float* yb1,
                                             const float* Ws2, const float* __restrict__ b2,
                                             const float* Ws3, const float* __restrict__ b3,
                                             float* h1_0, float* h1_1,
                                             float* h2_0, float* h2_1,
                                             float* Gs0, float* Gs1,
                                             float* agg0, float* agg1,
                                             const unsigned char* ii, const unsigned char* jj,
                                             const unsigned short* jl, int tid)
{
    const int n   = tid >> 3;
    const int c0s = (tid & 7) * 8;
    const int rs    = n * 31 - ((n * (n - 1)) >> 1);
    const int iiend = rs + 31 - n;
    float g[2][8];
#pragma unroll
    for (int j = 0; j < 8; j++) { g[0][j] = 0.f; g[1][j] = 0.f; }
    int kcur = 0;

#pragma unroll 1
    for (int ch = 0; ch < 8; ch++) {
        const int p0 = ch * 64;
        // h1 = relu(ya[ii] + yb[jj]) (bias pre-folded into ya)
        for (int e = tid; e < 64 * 64; e += NT) {
            int pl = e >> 6, c = e & 63;
            int p = p0 + pl;
            int ia = ii[p] * 64 + c, ja = jj[p] * 64 + c;
            h1_0[e] = fmaxf(ya0[ia] + yb0[ja], 0.f);
            h1_1[e] = fmaxf(ya1[ia] + yb1[ja], 0.f);
        }
        __syncthreads();
        gemm64_2(h1_0, h1_1, Ws2, b2, h2_0, h2_1, tid);
        __syncthreads();
        // signed sparse scatter into register G (both batches)
        int lo = max(rs, p0), hi = min(iiend, p0 + 64);
        for (int p = lo; p < hi; p++) {
            const float* r0p = h2_0 + (p - p0) * H2S + c0s;
            const float* r1p = h2_1 + (p - p0) * H2S + c0s;
            float4 u0 = *(const float4*)(r0p), u1 = *(const float4*)(r0p + 4);
            float4 v0 = *(const float4*)(r1p), v1 = *(const float4*)(r1p + 4);
            g[0][0] += u0.x; g[0][1] += u0.y; g[0][2] += u0.z; g[0][3] += u0.w;
            g[0][4] += u1.x; g[0][5] += u1.y; g[0][6] += u1.z; g[0][7] += u1.w;
            g[1][0] += v0.x; g[1][1] += v0.y; g[1][2] += v0.z; g[1][3] += v0.w;
            g[1][4] += v1.x; g[1][5] += v1.y; g[1][6] += v1.z; g[1][7] += v1.w;
        }
        while (kcur < n) {
            int p = jl[(n << 5) + kcur];
            if (p >= p0 + 64) break;
            const float* r0p = h2_0 + (p - p0) * H2S + c0s;
            const float* r1p = h2_1 + (p - p0) * H2S + c0s;
            float4 u0 = *(const float4*)(r0p), u1 = *(const float4*)(r0p + 4);
            float4 v0 = *(const float4*)(r1p), v1 = *(const float4*)(r1p + 4);
            g[0][0] -= u0.x; g[0][1] -= u0.y; g[0][2] -= u0.z; g[0][3] -= u0.w;
            g[0][4] -= u1.x; g[0][5] -= u1.y; g[0][6] -= u1.z; g[0][7] -= u1.w;
            g[1][0] -= v0.x; g[1][1] -= v0.y; g[1][2] -= v0.z; g[1][3] -= v0.w;
            g[1][4] -= v1.x; g[1][5] -= v1.y; g[1][6] -= v1.z; g[1][7] -= v1.w;
            kcur++;
        }
    }
#pragma unroll
    for (int j = 0; j < 8; j++) {
        Gs0[n * 64 + c0s + j] = g[0][j];
        Gs1[n * 64 + c0s + j] = g[1][j];
    }
    __syncthreads();
    aggGemm_2(Gs0, Gs1, Ws3, b3, agg0, agg1, tid);
    __syncthreads();
}

// smem layout (float offsets); two batches where doubled
#define OFF_H1    0        // 2 x 64*64
#define OFF_H2    8192     // 2 x 64*68
#define OFF_YA    16896    // 2 x 32*64
#define OFF_YB    20992
#define OFF_AGG   25088
#define OFF_ZC    29184
#define OFF_W2    33280    // 64*64
#define OFF_W3    37376    // 64*64
#define OFF_WLE1  41472    // 128*64
#define SMEM_FLOATS 49664
#define SMEM_BYTES  (SMEM_FLOATS * 4 + 2048 + 1024)

__global__ void __launch_bounds__(NT, 1)
RelationalLatentDynamics_82849919140105_kernel(Params P)
{
    extern __shared__ float sm[];
    float* h1_0 = sm + OFF_H1;       float* h1_1 = h1_0 + 4096;
    float* h2_0 = sm + OFF_H2;       float* h2_1 = h2_0 + 4352;
    float* ya0  = sm + OFF_YA;       float* ya1  = ya0 + 2048;
    float* yb0  = sm + OFF_YB;       float* yb1  = yb0 + 2048;
    float* agg0 = sm + OFF_AGG;      float* agg1 = agg0 + 2048;
    float* zc0  = sm + OFF_ZC;       float* zc1  = zc0 + 2048;
    float* s_w2   = sm + OFF_W2;
    float* s_w3   = sm + OFF_W3;
    float* s_wle1 = sm + OFF_WLE1;
    unsigned short* s_jl = (unsigned short*)(sm + SMEM_FLOATS);
    unsigned char*  s_ii = (unsigned char*)(s_jl + 1024);
    unsigned char*  s_jj = s_ii + 512;

    const int tid = threadIdx.x;
    const int c0 = (tid & 15) * 4;
    const int r0 = (tid >> 4) * 2;

    // pair index tables (padded to 512)
    for (int p = tid; p < 512; p += NT) {
        if (p < 496) {
            int pp = p, i = 0;
            while (pp >= 31 - i) { pp -= 31 - i; i++; }
            s_ii[p] = (unsigned char)i;
            s_jj[p] = (unsigned char)(i + 1 + pp);
        } else {
            s_ii[p] = 0; s_jj[p] = 1;
        }
    }
    for (int idx = tid; idx < 1024; idx += NT) {
        int n = idx >> 5, k = idx & 31;
        s_jl[idx] = (k < n)
            ? (unsigned short)(k * 31 - ((k * (k - 1)) >> 1) + (n - k - 1))
            : (unsigned short)0xFFFF;
    }
    // stage ee2/ee3 and le1 weights
    for (int idx = tid; idx < 4096; idx += NT) {
        s_w2[idx] = P.ee2_w[idx];
        s_w3[idx] = P.ee3_w[idx];
    }
    for (int idx = tid; idx < 8192; idx += NT) s_wle1[idx] = P.le1_w[idx];

    const float* zb0 = P.z + (size_t)(2 * blockIdx.x) * (16 * 32 * 32);
    const float* zb1 = zb0 + 16 * 32 * 32;

    // ---- Phase A: yaX/ybX = srcX @ ee1_w (streamed, register acc; b1 folded into ya) ----
    {
        float accA[2][2][4], accB[2][2][4];
#pragma unroll
        for (int j = 0; j < 4; j++) {
            float bv = P.ee1_b[c0 + j];
            accA[0][0][j] = bv; accA[0][1][j] = bv; accA[1][0][j] = bv; accA[1][1][j] = bv;
            accB[0][0][j] = 0.f; accB[0][1][j] = 0.f; accB[1][0][j] = 0.f; accB[1][1][j] = 0.f;
        }
#pragma unroll 1
        for (int ch = 0; ch < 8; ch++) {
            for (int idx = tid; idx < 2048; idx += NT) {
                int o = idx >> 6, fl = idx & 63;
                int t = 2 * ch + (fl >> 5), e = fl & 31;
                int off = (t * 32 + o) * 32 + e;
                float v0 = zb0[off], v1 = zb1[off];
                if (t > 0) {
                    int om = off - 1024;
                    v0 -= zb0[om]; v1 -= zb1[om];
                }
                h1_0[o * 64 + fl] = v0;
                h1_1[o * 64 + fl] = v1;
            }
            __syncthreads();
            acc_chunk2(h1_0, h1_1, P.ee1_w + ch * 4096, accA, r0, c0);
            acc_chunk2(h1_0, h1_1, P.ee1_w + 512 * 64 + ch * 4096, accB, r0, c0);
            __syncthreads();
        }
#pragma unroll
        for (int i = 0; i < 2; i++)
#pragma unroll
            for (int j = 0; j < 4; j++) {
                ya0[(r0 + i) * 64 + c0 + j] = accA[0][i][j];
                ya1[(r0 + i) * 64 + c0 + j] = accA[1][i][j];
                yb0[(r0 + i) * 64 + c0 + j] = accB[0][i][j];
                yb1[(r0 + i) * 64 + c0 + j] = accB[1][i][j];
            }
    }
    __syncthreads();

    // ---- ee edge block ----
    edge_block_2(ya0, ya1, yb0, yb1, s_w2, P.ee2_b, s_w3, P.ee3_b,
                 h1_0, h1_1, h2_0, h2_1, yb0, yb1, agg0, agg1,
                 s_ii, s_jj, s_jl, tid);

    // ---- ne MLP ----
    layer2<64, false, false>(agg0, agg1, P.ne1_w + 512 * 64, P.ne1_b, ya0, ya1, tid);
    {
        float acc[2][2][4];
#pragma unroll
        for (int i = 0; i < 2; i++)
#pragma unroll
            for (int j = 0; j < 4; j++) {
                acc[0][i][j] = ya0[(r0 + i) * 64 + c0 + j];   // own cells
                acc[1][i][j] = ya1[(r0 + i) * 64 + c0 + j];
            }
#pragma unroll 1
        for (int ch = 0; ch < 8; ch++) {
            for (int idx = tid; idx < 2048; idx += NT) {
                int o = idx >> 6, fl = idx & 63;
                int t = 2 * ch + (fl >> 5), e = fl & 31;
                int off = (t * 32 + o) * 32 + e;
                float v0 = zb0[off], v1 = zb1[off];
                if (t > 0) {
                    int om = off - 1024;
                    v0 -= zb0[om]; v1 -= zb1[om];
                }
                h1_0[o * 64 + fl] = v0;
                h1_1[o * 64 + fl] = v1;
            }
            __syncthreads();
            acc_chunk2(h1_0, h1_1, P.ne1_w + ch * 4096, acc, r0, c0);
            __syncthreads();
        }
#pragma unroll
        for (int i = 0; i < 2; i++)
#pragma unroll
            for (int j = 0; j < 4; j++) {
                ya0[(r0 + i) * 64 + c0 + j] = fmaxf(acc[0][i][j], 0.f);
                ya1[(r0 + i) * 64 + c0 + j] = fmaxf(acc[1][i][j], 0.f);
            }
    }
    __syncthreads();
    layer2<64, false, true>(ya0, ya1, P.ne2_w, P.ne2_b, h1_0, h1_1, tid);
    __syncthreads();
    layer_small_2(h1_0, h1_1, 64, P.ne3_w, P.ne3_b, h2_0, h2_1, 32, true, tid);
    __syncthreads();
    layer_small_2(h2_0, h2_1, 32, P.ne4_w, P.ne4_b, h1_0, h1_1, 32, false, tid);  // z_impl
    __syncthreads();

    // zc = concat(z[b,-1], z_impl); restage w2/w3 with le weights
    const float* zl0 = zb0 + 15 * 32 * 32;
    const float* zl1 = zb1 + 15 * 32 * 32;
    for (int idx = tid; idx < 2048; idx += NT) {
        int o = idx >> 6, c = idx & 63;
        zc0[idx] = (c < 32) ? zl0[o * 32 + c] : h1_0[o * 32 + (c - 32)];
        zc1[idx] = (c < 32) ? zl1[o * 32 + c] : h1_1[o * 32 + (c - 32)];
    }
    for (int idx = tid; idx < 4096; idx += NT) {
        s_w2[idx] = P.le2_w[idx];
        s_w3[idx] = P.le3_w[idx];
    }
    __syncthreads();

    // ---- rollout ----
    const int ostride = P.t_future * 1024;
    float* out0 = P.out + (size_t)(2 * blockIdx.x) * ostride;
    float* out1 = out0 + ostride;
#pragma unroll 1
    for (int t = 0; t < P.t_future; t++) {
        layer2<64, false, false>(zc0, zc1, s_wle1,           P.le1_b, ya0, ya1, tid);
        layer2<64, false, false>(zc0, zc1, s_wle1 + 64 * 64, nullptr, yb0, yb1, tid);
        __syncthreads();
        edge_block_2(ya0, ya1, yb0, yb1, s_w2, P.le2_b, s_w3, P.le3_b,
                     h1_0, h1_1, h2_0, h2_1, yb0, yb1, agg0, agg1,
                     s_ii, s_jj, s_jl, tid);

        layer2<64, false, false>(zc0, zc1, P.lt1_w,            P.lt1_b, h1_0, h1_1, tid);
        layer2<64, true,  true >(agg0, agg1, P.lt1_w + 64 * 64, nullptr, h1_0, h1_1, tid);
        __syncthreads();
        layer2<64, false, true>(h1_0, h1_1, P.lt2_w, P.lt2_b, h2_0, h2_1, tid);
        __syncthreads();
        layer_small_2(h2_0, h2_1, 64, P.lt3_w, P.lt3_b, h1_0, h1_1, 32, true, tid);
        __syncthreads();
        layer_small_2(h1_0, h1_1, 32, P.lt4_w, P.lt4_b, h2_0, h2_1, 16, true, tid);
        __syncthreads();
        layer2<16, false, false>(h2_0, h2_1, P.lt5_w, P.lt5_b, h1_0, h1_1, tid);  // delta
        __syncthreads();

        for (int idx = tid; idx < 2048; idx += NT) {
            float zn0 = zc0[idx] + h1_0[idx];
            float zn1 = zc1[idx] + h1_1[idx];
            zc0[idx] = zn0; zc1[idx] = zn1;
            int o = idx >> 6, c = idx & 63;
            if (c < 32) {
                out0[t * 1024 + o * 32 + c] = zn0;
                out1[t * 1024 + o * 32 + c] = zn1;
            }
        }
        __syncthreads();
    }
}

extern "C" void kernel_launch(void* const* d_in, const int* in_sizes, int n_in,
                              void* d_out, int out_size)
{
    Params P;
    int i = 0;
    P.z     = (const float*)d_in[i++];
    P.ee1_w = (const float*)d_in[i++]; P.ee1_b = (const float*)d_in[i++];
    P.ee2_w = (const float*)d_in[i++]; P.ee2_b = (const float*)d_in[i++];
    P.ee3_w = (const float*)d_in[i++]; P.ee3_b = (const float*)d_in[i++];
    P.ne1_w = (const float*)d_in[i++]; P.ne1_b = (const float*)d_in[i++];
    P.ne2_w = (const float*)d_in[i++]; P.ne2_b = (const float*)d_in[i++];
    P.ne3_w = (const float*)d_in[i++]; P.ne3_b = (const float*)d_in[i++];
    P.ne4_w = (const float*)d_in[i++]; P.ne4_b = (const float*)d_in[i++];
    P.le1_w = (const float*)d_in[i++]; P.le1_b = (const float*)d_in[i++];
    P.le2_w = (const float*)d_in[i++]; P.le2_b = (const float*)d_in[i++];
    P.le3_w = (const float*)d_in[i++]; P.le3_b = (const float*)d_in[i++];
    P.lt1_w = (const float*)d_in[i++]; P.lt1_b = (const float*)d_in[i++];
    P.lt2_w = (const float*)d_in[i++]; P.lt2_b = (const float*)d_in[i++];
    P.lt3_w = (const float*)d_in[i++]; P.lt3_b = (const float*)d_in[i++];
    P.lt4_w = (const float*)d_in[i++]; P.lt4_b = (const float*)d_in[i++];
    P.lt5_w = (const float*)d_in[i++]; P.lt5_b = (const float*)d_in[i++];
    P.out = (float*)d_out;
    P.t_future = out_size / (256 * 32 * 32);

    cudaFuncSetAttribute(RelationalLatentDynamics_82849919140105_kernel,
                         cudaFuncAttributeMaxDynamicSharedMemorySize, SMEM_BYTES);
    RelationalLatentDynamics_82849919140105_kernel<<<128, NT, SMEM_BYTES>>>(P);
}